// round 7
// baseline (speedup 1.0000x reference)
#include <cuda_runtime.h>
#include <math.h>
#include <stdint.h>

// Problem constants: B=2, S=2048, C=64, F=64, K=3
#define Bn   2
#define Sn   2048
#define Cn   64
#define Fn   64
#define Kt   3
#define TS   16               // output s-rows per block
#define RMAX 32               // D-window rows computed per block
#define XSTR 36               // xs row stride (words), 16B-aligned quads
#define Mtot (Bn * Sn)        // 4096

typedef unsigned long long ull;

__device__ __forceinline__ ull pack2(float lo, float hi) {
    ull r; asm("mov.b64 %0, {%1,%2};" : "=l"(r) : "f"(lo), "f"(hi)); return r;
}
__device__ __forceinline__ void fma2(ull& d, ull a, ull b) {
    asm("fma.rn.f32x2 %0, %1, %2, %0;" : "+l"(d) : "l"(a), "l"(b));
}
__device__ __forceinline__ float2 unpack2(ull v) {
    float2 f; asm("mov.b64 {%0,%1}, %2;" : "=f"(f.x), "=f"(f.y) : "l"(v)); return f;
}
// 128-bit shared load straight into two packed f32x2 operands (no mov packing).
__device__ __forceinline__ void lds_v2u64(ull& a, ull& b, const float* p) {
    uint32_t addr = (uint32_t)__cvta_generic_to_shared(p);
    asm volatile("ld.shared.v2.u64 {%0,%1}, [%2];" : "=l"(a), "=l"(b) : "r"(addr));
}

// Single fused kernel. grid (256, 2), 128 threads.
// Block = 16 s-rows x 32 features (half h = blockIdx.y).
__global__ __launch_bounds__(128) void ddc_one(
    const float* __restrict__ x,   // (B,S,C)
    const float* __restrict__ kw,  // (F,C,K)
    const float* __restrict__ ow,  // (F,)
    const void*  __restrict__ dilp,
    float*       __restrict__ out) // (B,S,F)
{
    __shared__ __align__(16) float xs[Cn * XSTR];  // x window transposed: xs[c*36 + r]
    __shared__ __align__(16) float ws[Cn * 96];    // ws[c*96 + k*32 + fr]; reused as D

    const int tid = threadIdx.x;
    const int h   = blockIdx.y;
    const int rq0 = blockIdx.x * TS;
    const int b   = rq0 >> 11;            // S = 2048
    const int s0  = rq0 & (Sn - 1);
    const int tx  = tid & 31;             // lane = feature fr
    const int ty  = tid >> 5;             // warp id 0..3

    // --- dilation decode + per-lane offset (redundant per warp; no sync needed) ---
    int dil = *(const int*)dilp;                                // int32/int64 LE
    if (dil < 1 || dil > 65536) dil = (int)(*(const float*)dilp);

    const int f  = h * 32 + tx;
    float mo  = 0.5f * (float)Sn / (float)(dil * Kt);
    float off = -mo / (1.0f + expf(-ow[f]));                    // -sigmoid*max_off
    float fl  = floorf(off);
    const int   I = (int)fl;
    const float w = off - fl;

    // Warp-local Imin/Imax butterfly (each warp holds all 32 features of this half).
    int Imn = I, Imx = I;
    #pragma unroll
    for (int o = 16; o; o >>= 1) {
        Imn = min(Imn, __shfl_xor_sync(0xffffffffu, Imn, o));
        Imx = max(Imx, __shfl_xor_sync(0xffffffffu, Imx, o));
    }

    int lo = s0 + Imn - (Kt - 1) * dil; if (lo < 0) lo = 0;
    int hi = s0 + TS - 1 + Imx + 1;     if (hi > Sn - 1) hi = Sn - 1;
    const bool ok = (hi - lo + 1) <= RMAX;   // identical across all warps

    if (ok) {
        // --- Stage x window transposed: 32 rows x 64 c, float4 global reads ---
        const float4* x4 = (const float4*)(x + b * Sn * Cn);
        #pragma unroll
        for (int it = 0; it < (RMAX * Cn / 4) / 128; it++) {     // 4 iters
            int idx = tid + it * 128;                            // < 512
            int r = idx >> 4, q = idx & 15;
            int gr = lo + r; if (gr > Sn - 1) gr = Sn - 1;
            float4 v = x4[gr * 16 + q];
            int c0 = q * 4;
            xs[(c0    ) * XSTR + r] = v.x;
            xs[(c0 + 1) * XSTR + r] = v.y;
            xs[(c0 + 2) * XSTR + r] = v.z;
            xs[(c0 + 3) * XSTR + r] = v.w;
        }
        // --- Stage weights transposed: 32 f x 192, float4 global reads ---
        const float4* kw4 = (const float4*)(kw + h * 32 * (Cn * Kt));
        #pragma unroll
        for (int it = 0; it < 12; it++) {
            int idx = tid + it * 128;                            // < 1536
            int fr2 = idx / 48, m = idx - fr2 * 48;
            float4 v = kw4[fr2 * 48 + m];
            int t = 4 * m;
            { int c = (t    ) / 3, k = (t    ) - 3 * c; ws[c * 96 + k * 32 + fr2] = v.x; }
            { int c = (t + 1) / 3, k = (t + 1) - 3 * c; ws[c * 96 + k * 32 + fr2] = v.y; }
            { int c = (t + 2) / 3, k = (t + 2) - 3 * c; ws[c * 96 + k * 32 + fr2] = v.z; }
            { int c = (t + 3) / 3, k = (t + 3) - 3 * c; ws[c * 96 + k * 32 + fr2] = v.w; }
        }
        __syncthreads();

        // --- MMA: warp ty owns rows quads ty and ty+4 (8 rows), lane tx cols tx+32j ---
        ull acc[4][3];
        #pragma unroll
        for (int i = 0; i < 4; i++)
            #pragma unroll
            for (int j = 0; j < 3; j++) acc[i][j] = 0ull;

        #pragma unroll 8
        for (int c = 0; c < Cn; c++) {
            ull xa, xb, xc, xd;
            lds_v2u64(xa, xb, xs + c * XSTR + 4 * ty);           // rows 4ty..4ty+3
            lds_v2u64(xc, xd, xs + c * XSTR + 16 + 4 * ty);      // rows 16+4ty..+3
            #pragma unroll
            for (int j = 0; j < 3; j++) {
                float wsc = ws[c * 96 + tx + 32 * j];            // conflict-free
                ull wv = pack2(wsc, wsc);
                fma2(acc[0][j], xa, wv);
                fma2(acc[1][j], xb, wv);
                fma2(acc[2][j], xc, wv);
                fma2(acc[3][j], xd, wv);
            }
        }
        __syncthreads();   // all ws reads done before overwrite

        // --- Dump D (32 x 96) into ws region ---
        float* D = ws;
        #pragma unroll
        for (int i = 0; i < 4; i++) {
            int r0 = (i < 2) ? (4 * ty + 2 * i) : (16 + 4 * ty + 2 * (i - 2));
            #pragma unroll
            for (int j = 0; j < 3; j++) {
                float2 v = unpack2(acc[i][j]);
                D[(r0    ) * 96 + tx + 32 * j] = v.x;
                D[(r0 + 1) * 96 + tx + 32 * j] = v.y;
            }
        }
        __syncthreads();

        // --- Gather + lerp; coalesced stores ---
        #pragma unroll
        for (int jj = 0; jj < 4; jj++) {
            int s = s0 + ty * 4 + jj;
            float y = 0.0f;
            #pragma unroll
            for (int k = 0; k < Kt; k++) {
                int i0  = s - k * dil + I;
                int i0c = min(max(i0,     0), Sn - 1);
                int i1c = min(max(i0 + 1, 0), Sn - 1);
                float d0 = D[(i0c - lo) * 96 + k * 32 + tx];
                float d1 = D[(i1c - lo) * 96 + k * 32 + tx];
                y += d0 + w * (d1 - d0);
            }
            out[(rq0 + ty * 4 + jj) * Fn + f] = y;
        }
    } else {
        // Correct fallback for pathological offset spread (never triggers here).
        for (int jj = 0; jj < 4; jj++) {
            int s = s0 + ty * 4 + jj;
            float y = 0.0f;
            for (int k = 0; k < Kt; k++) {
                int i0  = s - k * dil + I;
                int i0c = min(max(i0,     0), Sn - 1);
                int i1c = min(max(i0 + 1, 0), Sn - 1);
                float a0 = 0.0f, a1 = 0.0f;
                for (int c = 0; c < Cn; c++) {
                    float kk = kw[f * (Cn * Kt) + c * Kt + k];
                    a0 += x[(b * Sn + i0c) * Cn + c] * kk;
                    a1 += x[(b * Sn + i1c) * Cn + c] * kk;
                }
                y += a0 + w * (a1 - a0);
            }
            out[(rq0 + ty * 4 + jj) * Fn + f] = y;
        }
    }
}

extern "C" void kernel_launch(void* const* d_in, const int* in_sizes, int n_in,
                              void* d_out, int out_size)
{
    const float* x   = (const float*)d_in[0];   // (B,S,C) f32
    const float* kw  = (const float*)d_in[1];   // (F,C,K) f32
    const float* ow  = (const float*)d_in[2];   // (F,)    f32
    const void*  dil = d_in[3];                 // scalar dilation_rate

    dim3 grid(Mtot / TS, 2);
    ddc_one<<<grid, 128>>>(x, kw, ow, dil, (float*)d_out);
}

// round 8
// speedup vs baseline: 1.6094x; 1.6094x over previous
#include <cuda_runtime.h>
#include <math.h>
#include <stdint.h>

// Problem constants: B=2, S=2048, C=64, F=64, K=3
#define Bn   2
#define Sn   2048
#define Cn   64
#define Fn   64
#define Kt   3
#define TS   16               // output s-rows per block
#define RMAX 32               // D-window rows computed per block
#define XSTR 34               // xs row stride (even -> LDS.64-aligned, 2-way max)
#define WSTR 33               // ws stride (odd -> conflict-free both ways)
#define Mtot (Bn * Sn)        // 4096

typedef unsigned long long ull;

__device__ __forceinline__ ull pack2(float lo, float hi) {
    ull r; asm("mov.b64 %0, {%1,%2};" : "=l"(r) : "f"(lo), "f"(hi)); return r;
}
__device__ __forceinline__ void fma2(ull& d, ull a, ull b) {
    asm("fma.rn.f32x2 %0, %1, %2, %0;" : "+l"(d) : "l"(a), "l"(b));
}
__device__ __forceinline__ float2 unpack2(ull v) {
    float2 f; asm("mov.b64 {%0,%1}, %2;" : "=f"(f.x), "=f"(f.y) : "l"(v)); return f;
}

// Single fused kernel. grid (256, 2), 256 threads (8 warps).
// Block = 16 s-rows x 32 features (half h = blockIdx.y).
__global__ __launch_bounds__(256) void ddc_one(
    const float* __restrict__ x,   // (B,S,C)
    const float* __restrict__ kw,  // (F,C,K)
    const float* __restrict__ ow,  // (F,)
    const void*  __restrict__ dilp,
    float*       __restrict__ out) // (B,S,F)
{
    __shared__ __align__(16) float xs[Cn * XSTR];        // xs[c*34 + r]
    __shared__ __align__(16) float ws[Cn * Kt * WSTR];   // ws[(c*3+k)*33 + fr]; reused as D

    const int tid = threadIdx.x;
    const int h   = blockIdx.y;
    const int rq0 = blockIdx.x * TS;
    const int b   = rq0 >> 11;            // S = 2048
    const int s0  = rq0 & (Sn - 1);
    const int tx  = tid & 31;             // lane = feature fr
    const int wy  = tid >> 5;             // warp id 0..7

    // --- dilation decode + per-lane offset (redundant per warp; no sync needed) ---
    int dil = *(const int*)dilp;                                // int32/int64 LE
    if (dil < 1 || dil > 65536) dil = (int)(*(const float*)dilp);

    const int f  = h * 32 + tx;
    float mo  = 0.5f * (float)Sn / (float)(dil * Kt);
    float off = -mo / (1.0f + expf(-ow[f]));                    // -sigmoid*max_off
    float fl  = floorf(off);
    const int   I = (int)fl;
    const float w = off - fl;

    // Warp-local Imin/Imax butterfly (every warp sees all 32 features of half h).
    int Imn = I, Imx = I;
    #pragma unroll
    for (int o = 16; o; o >>= 1) {
        Imn = min(Imn, __shfl_xor_sync(0xffffffffu, Imn, o));
        Imx = max(Imx, __shfl_xor_sync(0xffffffffu, Imx, o));
    }

    int lo = s0 + Imn - (Kt - 1) * dil; if (lo < 0) lo = 0;
    int hi = s0 + TS - 1 + Imx + 1;     if (hi > Sn - 1) hi = Sn - 1;
    const bool ok = (hi - lo + 1) <= RMAX;   // uniform across the block

    if (ok) {
        // --- Stage x window transposed: column-per-lane, conflict-light STS ---
        {
            const int c  = tid & 63;
            const int rb = (tid >> 6) * 8;           // 0,8,16,24
            const float* xcol = x + b * Sn * Cn + c;
            #pragma unroll
            for (int i = 0; i < 8; i++) {
                int gr = lo + rb + i; if (gr > Sn - 1) gr = Sn - 1;
                xs[c * XSTR + rb + i] = xcol[gr * Cn];   // coalesced LDG.32
            }
        }
        // --- Stage weights transposed, fully conflict-free ---
        // thread: fr2 = tid>>3 (0..31), m-base = tid&7; 6 float4 per thread.
        {
            const int fr2 = tid >> 3;
            const int mb  = tid & 7;
            const float4* kw4 = (const float4*)(kw + (h * 32 + fr2) * (Cn * Kt));
            #pragma unroll
            for (int it = 0; it < 6; it++) {
                int m = mb + 8 * it;                 // < 48
                float4 v = kw4[m];                   // kernel[f][.] elems t=4m..4m+3
                int t = 4 * m;                       // t = c*3 + k
                ws[(t    ) * WSTR + fr2] = v.x;      // banks (4m+i+fr2)%32: all distinct
                ws[(t + 1) * WSTR + fr2] = v.y;
                ws[(t + 2) * WSTR + fr2] = v.z;
                ws[(t + 3) * WSTR + fr2] = v.w;
            }
        }
        __syncthreads();

        // --- MMA: warp wy owns row-pairs {wy, wy+8} (rows 2wy,2wy+1,16+2wy,16+2wy+1) ---
        ull acc[2][3];
        #pragma unroll
        for (int i = 0; i < 2; i++)
            #pragma unroll
            for (int j = 0; j < 3; j++) acc[i][j] = 0ull;

        #pragma unroll 8
        for (int c = 0; c < Cn; c++) {
            float2 pa = *(const float2*)(xs + c * XSTR + 2 * wy);        // LDS.64 bcast
            float2 pb = *(const float2*)(xs + c * XSTR + 16 + 2 * wy);   // LDS.64 bcast
            ull xa = pack2(pa.x, pa.y);
            ull xb = pack2(pb.x, pb.y);
            #pragma unroll
            for (int j = 0; j < 3; j++) {
                float wsc = ws[(c * 3 + j) * WSTR + tx];                 // conflict-free
                ull wv = pack2(wsc, wsc);
                fma2(acc[0][j], xa, wv);
                fma2(acc[1][j], xb, wv);
            }
        }
        __syncthreads();   // all ws reads done before overwrite

        // --- Dump D (32 x 96, stride 96) into ws region; bank = fr -> conflict-free ---
        float* D = ws;
        #pragma unroll
        for (int i = 0; i < 2; i++) {
            int r0 = 2 * wy + 16 * i;
            #pragma unroll
            for (int j = 0; j < 3; j++) {
                float2 v = unpack2(acc[i][j]);
                D[(r0    ) * 96 + tx + 32 * j] = v.x;
                D[(r0 + 1) * 96 + tx + 32 * j] = v.y;
            }
        }
        __syncthreads();

        // --- Gather + lerp; warp wy handles s-rows {2wy, 2wy+1}; coalesced stores ---
        #pragma unroll
        for (int jj = 0; jj < 2; jj++) {
            int s = s0 + wy * 2 + jj;
            float y = 0.0f;
            #pragma unroll
            for (int k = 0; k < Kt; k++) {
                int i0  = s - k * dil + I;
                int i0c = min(max(i0,     0), Sn - 1);
                int i1c = min(max(i0 + 1, 0), Sn - 1);
                float d0 = D[(i0c - lo) * 96 + k * 32 + tx];
                float d1 = D[(i1c - lo) * 96 + k * 32 + tx];
                y += d0 + w * (d1 - d0);
            }
            out[(rq0 + wy * 2 + jj) * Fn + f] = y;
        }
    } else {
        // Correct fallback for pathological offset spread (never triggers here).
        for (int jj = 0; jj < 2; jj++) {
            int s = s0 + wy * 2 + jj;
            float y = 0.0f;
            for (int k = 0; k < Kt; k++) {
                int i0  = s - k * dil + I;
                int i0c = min(max(i0,     0), Sn - 1);
                int i1c = min(max(i0 + 1, 0), Sn - 1);
                float a0 = 0.0f, a1 = 0.0f;
                for (int c = 0; c < Cn; c++) {
                    float kk = kw[f * (Cn * Kt) + c * Kt + k];
                    a0 += x[(b * Sn + i0c) * Cn + c] * kk;
                    a1 += x[(b * Sn + i1c) * Cn + c] * kk;
                }
                y += a0 + w * (a1 - a0);
            }
            out[(rq0 + wy * 2 + jj) * Fn + f] = y;
        }
    }
}

extern "C" void kernel_launch(void* const* d_in, const int* in_sizes, int n_in,
                              void* d_out, int out_size)
{
    const float* x   = (const float*)d_in[0];   // (B,S,C) f32
    const float* kw  = (const float*)d_in[1];   // (F,C,K) f32
    const float* ow  = (const float*)d_in[2];   // (F,)    f32
    const void*  dil = d_in[3];                 // scalar dilation_rate

    dim3 grid(Mtot / TS, 2);
    ddc_one<<<grid, 256>>>(x, kw, ow, dil, (float*)d_out);
}

// round 9
// speedup vs baseline: 1.7759x; 1.1034x over previous
#include <cuda_runtime.h>
#include <math.h>
#include <stdint.h>

// Problem constants: B=2, S=2048, C=64, F=64, K=3
#define Bn   2
#define Sn   2048
#define Cn   64
#define Fn   64
#define Kt   3
#define TS   16               // output s-rows per block
#define RMAX 32               // D-window rows computed per block
#define XSTR 36               // xs row stride (quad-aligned for LDS.128)
#define WSTR 33               // ws stride (odd -> conflict-free both ways)
#define Mtot (Bn * Sn)        // 4096

typedef unsigned long long ull;

__device__ __forceinline__ ull pack2(float lo, float hi) {
    ull r; asm("mov.b64 %0, {%1,%2};" : "=l"(r) : "f"(lo), "f"(hi)); return r;
}
__device__ __forceinline__ void fma2(ull& d, ull a, ull b) {
    asm("fma.rn.f32x2 %0, %1, %2, %0;" : "+l"(d) : "l"(a), "l"(b));
}
__device__ __forceinline__ ull add2(ull a, ull b) {
    ull r; asm("add.rn.f32x2 %0, %1, %2;" : "=l"(r) : "l"(a), "l"(b)); return r;
}
__device__ __forceinline__ float2 unpack2(ull v) {
    float2 f; asm("mov.b64 {%0,%1}, %2;" : "=f"(f.x), "=f"(f.y) : "l"(v)); return f;
}
// 128-bit shared load into two packed f32x2 operands.
__device__ __forceinline__ void lds_v2u64(ull& a, ull& b, const float* p) {
    uint32_t addr = (uint32_t)__cvta_generic_to_shared(p);
    asm volatile("ld.shared.v2.u64 {%0,%1}, [%2];" : "=l"(a), "=l"(b) : "r"(addr));
}

// Single fused kernel. grid (256, 2), 256 threads (8 warps).
// Block = 16 s-rows x 32 features (half h = blockIdx.y).
// MMA: warp wy -> rows 8*(wy&3)..+7 over c-half (wy>>2); partials reduced in smem.
__global__ __launch_bounds__(256) void ddc_one(
    const float* __restrict__ x,   // (B,S,C)
    const float* __restrict__ kw,  // (F,C,K)
    const float* __restrict__ ow,  // (F,)
    const void*  __restrict__ dilp,
    float*       __restrict__ out) // (B,S,F)
{
    __shared__ __align__(16) float xs[Cn * XSTR];        // xs[c*36 + r]       9.2 KB
    __shared__ __align__(16) float ws[Cn * Kt * WSTR];   // ws[(c*3+k)*33+fr] 25.3 KB; reused as D[32][96]
    __shared__ __align__(16) ull   pbuf[4 * 12 * 32];    // partial accs      12.0 KB

    const int tid = threadIdx.x;
    const int h   = blockIdx.y;
    const int rq0 = blockIdx.x * TS;
    const int b   = rq0 >> 11;            // S = 2048
    const int s0  = rq0 & (Sn - 1);
    const int tx  = tid & 31;             // lane = feature fr
    const int wy  = tid >> 5;             // warp id 0..7

    // --- dilation decode + per-lane offset (redundant per warp; no sync) ---
    int dil = *(const int*)dilp;                                // int32/int64 LE
    if (dil < 1 || dil > 65536) dil = (int)(*(const float*)dilp);

    const int f  = h * 32 + tx;
    float mo  = 0.5f * (float)Sn / (float)(dil * Kt);
    float off = -mo / (1.0f + expf(-ow[f]));                    // -sigmoid*max_off
    float fl  = floorf(off);
    const int   I = (int)fl;
    const float w = off - fl;

    // Warp-local Imin/Imax butterfly (every warp sees all 32 features of half h).
    int Imn = I, Imx = I;
    #pragma unroll
    for (int o = 16; o; o >>= 1) {
        Imn = min(Imn, __shfl_xor_sync(0xffffffffu, Imn, o));
        Imx = max(Imx, __shfl_xor_sync(0xffffffffu, Imx, o));
    }

    int lo = s0 + Imn - (Kt - 1) * dil; if (lo < 0) lo = 0;
    int hi = s0 + TS - 1 + Imx + 1;     if (hi > Sn - 1) hi = Sn - 1;
    const bool ok = (hi - lo + 1) <= RMAX;   // uniform across the block

    if (ok) {
        // --- Stage x window transposed: column-per-lane (coalesced LDG.32) ---
        {
            const int c  = tid & 63;
            const int rb = (tid >> 6) * 8;           // 0,8,16,24
            const float* xcol = x + b * Sn * Cn + c;
            #pragma unroll
            for (int i = 0; i < 8; i++) {
                int gr = lo + rb + i; if (gr > Sn - 1) gr = Sn - 1;
                xs[c * XSTR + rb + i] = xcol[gr * Cn];
            }
        }
        // --- Stage weights transposed, conflict-free (R8 scheme) ---
        {
            const int fr2 = tid >> 3;
            const int mb  = tid & 7;
            const float4* kw4 = (const float4*)(kw + (h * 32 + fr2) * (Cn * Kt));
            #pragma unroll
            for (int it = 0; it < 6; it++) {
                int m = mb + 8 * it;                 // < 48
                float4 v = kw4[m];
                int t = 4 * m;                       // t = c*3 + k
                ws[(t    ) * WSTR + fr2] = v.x;
                ws[(t + 1) * WSTR + fr2] = v.y;
                ws[(t + 2) * WSTR + fr2] = v.z;
                ws[(t + 3) * WSTR + fr2] = v.w;
            }
        }
        __syncthreads();

        // --- MMA: warp (wp = wy&3) rows 8wp..8wp+7; c-half = wy>>2 ---
        const int wp    = wy & 3;
        const int cbase = (wy >> 2) * 32;
        ull acc[4][3];
        #pragma unroll
        for (int i = 0; i < 4; i++)
            #pragma unroll
            for (int j = 0; j < 3; j++) acc[i][j] = 0ull;

        #pragma unroll 8
        for (int cr = 0; cr < 32; cr++) {
            const int c = cbase + cr;
            ull xa, xb, xc, xd;
            lds_v2u64(xa, xb, xs + c * XSTR + 8 * wp);       // rows 8wp..8wp+3 (bcast)
            lds_v2u64(xc, xd, xs + c * XSTR + 8 * wp + 4);   // rows 8wp+4..8wp+7
            #pragma unroll
            for (int j = 0; j < 3; j++) {
                float wsc = ws[(c * 3 + j) * WSTR + tx];     // conflict-free
                ull wv = pack2(wsc, wsc);
                fma2(acc[0][j], xa, wv);
                fma2(acc[1][j], xb, wv);
                fma2(acc[2][j], xc, wv);
                fma2(acc[3][j], xd, wv);
            }
        }

        // --- Upper-half warps store partials (STS.64) ---
        if (wy >= 4) {
            ull* p = pbuf + ((wy - 4) * 12) * 32 + tx;
            #pragma unroll
            for (int i = 0; i < 4; i++)
                #pragma unroll
                for (int j = 0; j < 3; j++)
                    p[(i * 3 + j) * 32] = acc[i][j];
        }
        __syncthreads();   // partials visible; all ws reads done

        // --- Lower-half warps reduce + write D (32 x 96, stride 96) ---
        float* D = ws;
        if (wy < 4) {
            const ull* p = pbuf + (wp * 12) * 32 + tx;
            #pragma unroll
            for (int i = 0; i < 4; i++) {
                #pragma unroll
                for (int j = 0; j < 3; j++) {
                    ull s2 = add2(acc[i][j], p[(i * 3 + j) * 32]);
                    float2 v = unpack2(s2);
                    D[(8 * wp + 2 * i)     * 96 + tx + 32 * j] = v.x;  // bank = tx: cf
                    D[(8 * wp + 2 * i + 1) * 96 + tx + 32 * j] = v.y;
                }
            }
        }
        __syncthreads();

        // --- Gather + lerp; warp wy handles s-rows {2wy, 2wy+1}; coalesced stores ---
        #pragma unroll
        for (int jj = 0; jj < 2; jj++) {
            int s = s0 + wy * 2 + jj;
            float y = 0.0f;
            #pragma unroll
            for (int k = 0; k < Kt; k++) {
                int i0  = s - k * dil + I;
                int i0c = min(max(i0,     0), Sn - 1);
                int i1c = min(max(i0 + 1, 0), Sn - 1);
                float d0 = D[(i0c - lo) * 96 + k * 32 + tx];
                float d1 = D[(i1c - lo) * 96 + k * 32 + tx];
                y += d0 + w * (d1 - d0);
            }
            out[(rq0 + wy * 2 + jj) * Fn + f] = y;
        }
    } else {
        // Correct fallback for pathological offset spread (never triggers here).
        for (int jj = 0; jj < 2; jj++) {
            int s = s0 + wy * 2 + jj;
            float y = 0.0f;
            for (int k = 0; k < Kt; k++) {
                int i0  = s - k * dil + I;
                int i0c = min(max(i0,     0), Sn - 1);
                int i1c = min(max(i0 + 1, 0), Sn - 1);
                float a0 = 0.0f, a1 = 0.0f;
                for (int c = 0; c < Cn; c++) {
                    float kk = kw[f * (Cn * Kt) + c * Kt + k];
                    a0 += x[(b * Sn + i0c) * Cn + c] * kk;
                    a1 += x[(b * Sn + i1c) * Cn + c] * kk;
                }
                y += a0 + w * (a1 - a0);
            }
            out[(rq0 + wy * 2 + jj) * Fn + f] = y;
        }
    }
}

extern "C" void kernel_launch(void* const* d_in, const int* in_sizes, int n_in,
                              void* d_out, int out_size)
{
    const float* x   = (const float*)d_in[0];   // (B,S,C) f32
    const float* kw  = (const float*)d_in[1];   // (F,C,K) f32
    const float* ow  = (const float*)d_in[2];   // (F,)    f32
    const void*  dil = d_in[3];                 // scalar dilation_rate

    dim3 grid(Mtot / TS, 2);
    ddc_one<<<grid, 256>>>(x, kw, ow, dil, (float*)d_out);
}

// round 10
// speedup vs baseline: 1.8679x; 1.0518x over previous
#include <cuda_runtime.h>
#include <math.h>
#include <stdint.h>

// Problem constants: B=2, S=2048, C=64, F=64, K=3
#define Bn   2
#define Sn   2048
#define Cn   64
#define Fn   64
#define Kt   3
#define TS   32               // output s-rows per block
#define RMAX 48               // D-window rows computed per block
#define XSTR 52               // xs row stride: 52 ≡ 0 mod 4 -> LDS.128-aligned quads
#define WSTR 33               // ws stride (odd -> conflict-free both ways)
#define Mtot (Bn * Sn)        // 4096

typedef unsigned long long ull;

__device__ __forceinline__ ull pack2(float lo, float hi) {
    ull r; asm("mov.b64 %0, {%1,%2};" : "=l"(r) : "f"(lo), "f"(hi)); return r;
}
__device__ __forceinline__ void fma2(ull& d, ull a, ull b) {
    asm("fma.rn.f32x2 %0, %1, %2, %0;" : "+l"(d) : "l"(a), "l"(b));
}
__device__ __forceinline__ float2 unpack2(ull v) {
    float2 f; asm("mov.b64 {%0,%1}, %2;" : "=f"(f.x), "=f"(f.y) : "l"(v)); return f;
}
// 128-bit shared load into two packed f32x2 operands.
__device__ __forceinline__ void lds_v2u64(ull& a, ull& b, const float* p) {
    uint32_t addr = (uint32_t)__cvta_generic_to_shared(p);
    asm volatile("ld.shared.v2.u64 {%0,%1}, [%2];" : "=l"(a), "=l"(b) : "r"(addr));
}

// Single fused kernel. grid (128, 2), 128 threads (4 warps).
// Block = 32 s-rows x 32 features (half h = blockIdx.y).
// MMA: warp wy owns rows 12wy..12wy+11 over ALL c (no reduction needed).
__global__ __launch_bounds__(128) void ddc_one(
    const float* __restrict__ x,   // (B,S,C)
    const float* __restrict__ kw,  // (F,C,K)
    const float* __restrict__ ow,  // (F,)
    const void*  __restrict__ dilp,
    float*       __restrict__ out) // (B,S,F)
{
    __shared__ __align__(16) float xs[Cn * XSTR];        // xs[c*52 + r]       13.3 KB
    __shared__ __align__(16) float ws[Cn * Kt * WSTR];   // ws[(c*3+k)*33+fr]  25.3 KB; reused as D[48][96]

    const int tid = threadIdx.x;
    const int h   = blockIdx.y;
    const int rq0 = blockIdx.x * TS;
    const int b   = rq0 >> 11;            // S = 2048
    const int s0  = rq0 & (Sn - 1);
    const int tx  = tid & 31;             // lane = feature fr
    const int wy  = tid >> 5;             // warp id 0..3

    // --- dilation decode + per-lane offset (redundant per warp; no sync) ---
    int dil = *(const int*)dilp;                                // int32/int64 LE
    if (dil < 1 || dil > 65536) dil = (int)(*(const float*)dilp);

    const int f  = h * 32 + tx;
    float mo  = 0.5f * (float)Sn / (float)(dil * Kt);
    float off = -mo / (1.0f + expf(-ow[f]));                    // -sigmoid*max_off
    float fl  = floorf(off);
    const int   I = (int)fl;
    const float w = off - fl;

    // Warp-local Imin/Imax butterfly (every warp sees all 32 features of half h).
    int Imn = I, Imx = I;
    #pragma unroll
    for (int o = 16; o; o >>= 1) {
        Imn = min(Imn, __shfl_xor_sync(0xffffffffu, Imn, o));
        Imx = max(Imx, __shfl_xor_sync(0xffffffffu, Imx, o));
    }

    int lo = s0 + Imn - (Kt - 1) * dil; if (lo < 0) lo = 0;
    int hi = s0 + TS - 1 + Imx + 1;     if (hi > Sn - 1) hi = Sn - 1;
    const bool ok = (hi - lo + 1) <= RMAX;   // uniform across the block

    if (ok) {
        // --- Stage x window transposed: column-per-lane (coalesced LDG.32) ---
        {
            const int c  = tid & 63;
            const int rb = (tid >> 6) * 24;          // 0 or 24
            const float* xcol = x + b * Sn * Cn + c;
            #pragma unroll
            for (int i = 0; i < 24; i++) {
                int gr = lo + rb + i; if (gr > Sn - 1) gr = Sn - 1;
                xs[c * XSTR + rb + i] = xcol[gr * Cn];
            }
        }
        // --- Stage weights transposed, conflict-light ---
        {
            const int fr2 = tid >> 2;                // 0..31
            const int mb  = tid & 3;
            const float4* kw4 = (const float4*)(kw + (h * 32 + fr2) * (Cn * Kt));
            #pragma unroll
            for (int it = 0; it < 12; it++) {
                int m = mb + 4 * it;                 // < 48
                float4 v = kw4[m];
                int t = 4 * m;                       // t = c*3 + k
                ws[(t    ) * WSTR + fr2] = v.x;
                ws[(t + 1) * WSTR + fr2] = v.y;
                ws[(t + 2) * WSTR + fr2] = v.z;
                ws[(t + 3) * WSTR + fr2] = v.w;
            }
        }
        __syncthreads();

        // --- MMA: warp wy rows 12wy..12wy+11, all 64 c; acc = 6 row-pairs x 3 cols ---
        ull acc[6][3];
        #pragma unroll
        for (int p = 0; p < 6; p++)
            #pragma unroll
            for (int j = 0; j < 3; j++) acc[p][j] = 0ull;

        const int r0 = 12 * wy;
        #pragma unroll 8
        for (int c = 0; c < Cn; c++) {
            ull xv[6];
            lds_v2u64(xv[0], xv[1], xs + c * XSTR + r0);       // rows r0..r0+3 (bcast)
            lds_v2u64(xv[2], xv[3], xs + c * XSTR + r0 + 4);   // rows r0+4..r0+7
            lds_v2u64(xv[4], xv[5], xs + c * XSTR + r0 + 8);   // rows r0+8..r0+11
            #pragma unroll
            for (int j = 0; j < 3; j++) {
                float wsc = ws[(c * 3 + j) * WSTR + tx];       // conflict-free
                ull wv = pack2(wsc, wsc);
                #pragma unroll
                for (int p = 0; p < 6; p++) fma2(acc[p][j], xv[p], wv);
            }
        }
        __syncthreads();   // all ws reads done before overwrite

        // --- Dump D (48 x 96, stride 96) into ws region; bank = tx -> conflict-free ---
        float* D = ws;
        #pragma unroll
        for (int p = 0; p < 6; p++) {
            int r = r0 + 2 * p;
            #pragma unroll
            for (int j = 0; j < 3; j++) {
                float2 v = unpack2(acc[p][j]);
                D[(r    ) * 96 + tx + 32 * j] = v.x;
                D[(r + 1) * 96 + tx + 32 * j] = v.y;
            }
        }
        __syncthreads();

        // --- Gather + lerp; warp wy handles s-rows 8wy..8wy+7; coalesced stores ---
        #pragma unroll
        for (int jj = 0; jj < 8; jj++) {
            int s = s0 + wy * 8 + jj;
            float y = 0.0f;
            #pragma unroll
            for (int k = 0; k < Kt; k++) {
                int i0  = s - k * dil + I;
                int i0c = min(max(i0,     0), Sn - 1);
                int i1c = min(max(i0 + 1, 0), Sn - 1);
                float d0 = D[(i0c - lo) * 96 + k * 32 + tx];   // bank = tx: cf
                float d1 = D[(i1c - lo) * 96 + k * 32 + tx];
                y += d0 + w * (d1 - d0);
            }
            out[(rq0 + wy * 8 + jj) * Fn + f] = y;
        }
    } else {
        // Correct fallback for pathological offset spread (never triggers here).
        for (int jj = 0; jj < 8; jj++) {
            int s = s0 + wy * 8 + jj;
            float y = 0.0f;
            for (int k = 0; k < Kt; k++) {
                int i0  = s - k * dil + I;
                int i0c = min(max(i0,     0), Sn - 1);
                int i1c = min(max(i0 + 1, 0), Sn - 1);
                float a0 = 0.0f, a1 = 0.0f;
                for (int c = 0; c < Cn; c++) {
                    float kk = kw[f * (Cn * Kt) + c * Kt + k];
                    a0 += x[(b * Sn + i0c) * Cn + c] * kk;
                    a1 += x[(b * Sn + i1c) * Cn + c] * kk;
                }
                y += a0 + w * (a1 - a0);
            }
            out[(rq0 + wy * 8 + jj) * Fn + f] = y;
        }
    }
}

extern "C" void kernel_launch(void* const* d_in, const int* in_sizes, int n_in,
                              void* d_out, int out_size)
{
    const float* x   = (const float*)d_in[0];   // (B,S,C) f32
    const float* kw  = (const float*)d_in[1];   // (F,C,K) f32
    const float* ow  = (const float*)d_in[2];   // (F,)    f32
    const void*  dil = d_in[3];                 // scalar dilation_rate

    dim3 grid(Mtot / TS, 2);
    ddc_one<<<grid, 128>>>(x, kw, ow, dil, (float*)d_out);
}

// round 11
// speedup vs baseline: 1.9227x; 1.0293x over previous
#include <cuda_runtime.h>
#include <math.h>
#include <stdint.h>

// Problem constants: B=2, S=2048, C=64, F=64, K=3
#define Bn   2
#define Sn   2048
#define Cn   64
#define Fn   64
#define Kt   3
#define TS   32               // output s-rows per block
#define RMAX 48               // D-window rows computed per block
#define XSTR 52               // xs row stride: ≡0 mod 4 -> LDS.128-aligned quads
#define WSTR 33               // ws stride (odd -> conflict-free both ways)
#define Mtot (Bn * Sn)        // 4096

typedef unsigned long long ull;

__device__ __forceinline__ ull pack2(float lo, float hi) {
    ull r; asm("mov.b64 %0, {%1,%2};" : "=l"(r) : "f"(lo), "f"(hi)); return r;
}
__device__ __forceinline__ void fma2(ull& d, ull a, ull b) {
    asm("fma.rn.f32x2 %0, %1, %2, %0;" : "+l"(d) : "l"(a), "l"(b));
}
__device__ __forceinline__ float2 unpack2(ull v) {
    float2 f; asm("mov.b64 {%0,%1}, %2;" : "=f"(f.x), "=f"(f.y) : "l"(v)); return f;
}
// 128-bit shared load into two packed f32x2 operands.
__device__ __forceinline__ void lds_v2u64(ull& a, ull& b, const float* p) {
    uint32_t addr = (uint32_t)__cvta_generic_to_shared(p);
    asm volatile("ld.shared.v2.u64 {%0,%1}, [%2];" : "=l"(a), "=l"(b) : "r"(addr));
}

// Single fused kernel. grid (128, 2), 256 threads (8 warps).
// Block = 32 s-rows x 32 features (half h = blockIdx.y).
// MMA: warp wy -> rows 12*(wy&3)..+11 over c-half (wy>>2).
// Reduction: lower warps write accs into D, upper warps add into D.
__global__ __launch_bounds__(256) void ddc_one(
    const float* __restrict__ x,   // (B,S,C)
    const float* __restrict__ kw,  // (F,C,K)
    const float* __restrict__ ow,  // (F,)
    const void*  __restrict__ dilp,
    float*       __restrict__ out) // (B,S,F)
{
    __shared__ __align__(16) float xs[Cn * XSTR];        // xs[c*52 + r]       13.3 KB
    __shared__ __align__(16) float ws[Cn * Kt * WSTR];   // ws[(c*3+k)*33+fr]  25.3 KB; reused as D[48][96]

    const int tid = threadIdx.x;
    const int h   = blockIdx.y;
    const int rq0 = blockIdx.x * TS;
    const int b   = rq0 >> 11;            // S = 2048
    const int s0  = rq0 & (Sn - 1);
    const int tx  = tid & 31;             // lane = feature fr
    const int wy  = tid >> 5;             // warp id 0..7

    // --- dilation decode + per-lane offset (redundant per warp; no sync) ---
    int dil = *(const int*)dilp;                                // int32/int64 LE
    if (dil < 1 || dil > 65536) dil = (int)(*(const float*)dilp);

    const int f  = h * 32 + tx;
    float mo  = 0.5f * (float)Sn / (float)(dil * Kt);
    float off = -mo / (1.0f + expf(-ow[f]));                    // -sigmoid*max_off
    float fl  = floorf(off);
    const int   I = (int)fl;
    const float w = off - fl;

    // Warp-local Imin/Imax butterfly (every warp sees all 32 features of half h).
    int Imn = I, Imx = I;
    #pragma unroll
    for (int o = 16; o; o >>= 1) {
        Imn = min(Imn, __shfl_xor_sync(0xffffffffu, Imn, o));
        Imx = max(Imx, __shfl_xor_sync(0xffffffffu, Imx, o));
    }

    int lo = s0 + Imn - (Kt - 1) * dil; if (lo < 0) lo = 0;
    int hi = s0 + TS - 1 + Imx + 1;     if (hi > Sn - 1) hi = Sn - 1;
    const bool ok = (hi - lo + 1) <= RMAX;   // uniform across the block

    if (ok) {
        // --- Stage x window transposed: column-per-lane (coalesced LDG.32) ---
        {
            const int c  = tid & 63;
            const int rb = (tid >> 6) * 12;          // 0,12,24,36
            const float* xcol = x + b * Sn * Cn + c;
            #pragma unroll
            for (int i = 0; i < 12; i++) {
                int gr = lo + rb + i; if (gr > Sn - 1) gr = Sn - 1;
                xs[c * XSTR + rb + i] = xcol[gr * Cn];
            }
        }
        // --- Stage weights transposed, conflict-free (R8 scheme, 256 thr) ---
        {
            const int fr2 = tid >> 3;                // 0..31
            const int mb  = tid & 7;
            const float4* kw4 = (const float4*)(kw + (h * 32 + fr2) * (Cn * Kt));
            #pragma unroll
            for (int it = 0; it < 6; it++) {
                int m = mb + 8 * it;                 // < 48
                float4 v = kw4[m];
                int t = 4 * m;                       // t = c*3 + k
                ws[(t    ) * WSTR + fr2] = v.x;
                ws[(t + 1) * WSTR + fr2] = v.y;
                ws[(t + 2) * WSTR + fr2] = v.z;
                ws[(t + 3) * WSTR + fr2] = v.w;
            }
        }
        __syncthreads();

        // --- MMA: warp wp = wy&3 rows 12wp..+11; c-half = wy>>2 (32 c each) ---
        const int wp    = wy & 3;
        const int cbase = (wy >> 2) * 32;
        const int r0    = 12 * wp;
        ull acc[6][3];
        #pragma unroll
        for (int p = 0; p < 6; p++)
            #pragma unroll
            for (int j = 0; j < 3; j++) acc[p][j] = 0ull;

        #pragma unroll 8
        for (int cr = 0; cr < 32; cr++) {
            const int c = cbase + cr;
            ull xv[6];
            lds_v2u64(xv[0], xv[1], xs + c * XSTR + r0);       // rows r0..r0+3 (bcast)
            lds_v2u64(xv[2], xv[3], xs + c * XSTR + r0 + 4);
            lds_v2u64(xv[4], xv[5], xs + c * XSTR + r0 + 8);
            #pragma unroll
            for (int j = 0; j < 3; j++) {
                float wsc = ws[(c * 3 + j) * WSTR + tx];       // conflict-free
                ull wv = pack2(wsc, wsc);
                #pragma unroll
                for (int p = 0; p < 6; p++) fma2(acc[p][j], xv[p], wv);
            }
        }
        __syncthreads();   // all ws reads done before overwrite

        // --- Phase 1: lower warps (c-half 0) write accs into D (48x96, stride 96) ---
        float* D = ws;
        if (wy < 4) {
            #pragma unroll
            for (int p = 0; p < 6; p++) {
                int r = r0 + 2 * p;
                #pragma unroll
                for (int j = 0; j < 3; j++) {
                    float2 v = unpack2(acc[p][j]);
                    D[(r    ) * 96 + tx + 32 * j] = v.x;       // bank = tx: cf
                    D[(r + 1) * 96 + tx + 32 * j] = v.y;
                }
            }
        }
        __syncthreads();

        // --- Phase 2: upper warps (c-half 1) add into D ---
        if (wy >= 4) {
            #pragma unroll
            for (int p = 0; p < 6; p++) {
                int r = r0 + 2 * p;
                #pragma unroll
                for (int j = 0; j < 3; j++) {
                    float2 v = unpack2(acc[p][j]);
                    D[(r    ) * 96 + tx + 32 * j] += v.x;      // LDS+FADD+STS, cf
                    D[(r + 1) * 96 + tx + 32 * j] += v.y;
                }
            }
        }
        __syncthreads();

        // --- Gather + lerp; warp wy handles s-rows 4wy..4wy+3; coalesced stores ---
        #pragma unroll
        for (int jj = 0; jj < 4; jj++) {
            int s = s0 + wy * 4 + jj;
            float y = 0.0f;
            #pragma unroll
            for (int k = 0; k < Kt; k++) {
                int i0  = s - k * dil + I;
                int i0c = min(max(i0,     0), Sn - 1);
                int i1c = min(max(i0 + 1, 0), Sn - 1);
                float d0 = D[(i0c - lo) * 96 + k * 32 + tx];   // bank = tx: cf
                float d1 = D[(i1c - lo) * 96 + k * 32 + tx];
                y += d0 + w * (d1 - d0);
            }
            out[(rq0 + wy * 4 + jj) * Fn + f] = y;
        }
    } else {
        // Correct fallback for pathological offset spread (never triggers here).
        for (int jj = 0; jj < 4; jj++) {
            int s = s0 + wy * 4 + jj;
            float y = 0.0f;
            for (int k = 0; k < Kt; k++) {
                int i0  = s - k * dil + I;
                int i0c = min(max(i0,     0), Sn - 1);
                int i1c = min(max(i0 + 1, 0), Sn - 1);
                float a0 = 0.0f, a1 = 0.0f;
                for (int c = 0; c < Cn; c++) {
                    float kk = kw[f * (Cn * Kt) + c * Kt + k];
                    a0 += x[(b * Sn + i0c) * Cn + c] * kk;
                    a1 += x[(b * Sn + i1c) * Cn + c] * kk;
                }
                y += a0 + w * (a1 - a0);
            }
            out[(rq0 + wy * 4 + jj) * Fn + f] = y;
        }
    }
}

extern "C" void kernel_launch(void* const* d_in, const int* in_sizes, int n_in,
                              void* d_out, int out_size)
{
    const float* x   = (const float*)d_in[0];   // (B,S,C) f32
    const float* kw  = (const float*)d_in[1];   // (F,C,K) f32
    const float* ow  = (const float*)d_in[2];   // (F,)    f32
    const void*  dil = d_in[3];                 // scalar dilation_rate

    dim3 grid(Mtot / TS, 2);
    ddc_one<<<grid, 256>>>(x, kw, ow, dil, (float*)d_out);
}